// round 8
// baseline (speedup 1.0000x reference)
#include <cuda_runtime.h>
#include <cstdint>
#include <math.h>

#define NN 50000
#define NE 800000
#define HF 64

// ---------------- scratch (static device globals; no allocs) ----------------
__device__ __align__(256) float g_hA[NN * HF];
__device__ __align__(256) float g_hB[NN * HF];
__device__ __align__(256) float g_hn[NN * HF];
__device__ float g_he[NN];
__device__ float g_z[NN * 2];
__device__ int g_deg[NN];
__device__ int g_off[NN + 1];
__device__ int g_cur[NN];
__device__ int g_esrc[NE];

// ---------------- packed f32x2 helpers ----------------
#define FMA2(d, a, b, c) \
    asm("fma.rn.f32x2 %0, %1, %2, %3;" : "=l"(d) : "l"(a), "l"(b), "l"(c))

__device__ __forceinline__ unsigned long long pack_dup(float x) {
    unsigned long long r;
    unsigned int u = __float_as_uint(x);
    asm("mov.b64 %0, {%1, %1};" : "=l"(r) : "r"(u));
    return r;
}
__device__ __forceinline__ void unpack2(unsigned long long v, float& lo, float& hi) {
    unsigned int a, b;
    asm("mov.b64 {%0, %1}, %2;" : "=r"(a), "=r"(b) : "l"(v));
    lo = __uint_as_float(a);
    hi = __uint_as_float(b);
}

// ---------------- CSR build ----------------
__global__ void zero_kernel() {
    int i = blockIdx.x * blockDim.x + threadIdx.x;
    if (i < NN) { g_deg[i] = 0; g_he[i] = 0.0f; }
}

__global__ void hist_kernel(const int* __restrict__ dst, const float* __restrict__ ef) {
    int e = blockIdx.x * blockDim.x + threadIdx.x;
    if (e < NE) {
        int d = dst[e];
        atomicAdd(&g_deg[d], 1);
        atomicAdd(&g_he[d], ef[e]);
    }
}

// Single-block exclusive scan of g_deg -> g_off / g_cur (warp-shuffle based).
__global__ __launch_bounds__(1024) void scan_kernel() {
    __shared__ int warp_sums[32];
    __shared__ int s_carry;
    const int tid = threadIdx.x;
    const int lane = tid & 31;
    const int wid = tid >> 5;
    if (tid == 0) s_carry = 0;
    __syncthreads();

    const int CHUNK = 1024 * 4;
    for (int base = 0; base < NN; base += CHUNK) {
        int v[4];
        int i0 = base + tid * 4;
#pragma unroll
        for (int j = 0; j < 4; j++) {
            int i = i0 + j;
            v[j] = (i < NN) ? g_deg[i] : 0;
        }
        int tsum = v[0] + v[1] + v[2] + v[3];

        int x = tsum;  // inclusive warp scan of thread sums
#pragma unroll
        for (int off = 1; off < 32; off <<= 1) {
            int y = __shfl_up_sync(0xFFFFFFFFu, x, off);
            if (lane >= off) x += y;
        }
        if (lane == 31) warp_sums[wid] = x;
        __syncthreads();
        if (wid == 0) {
            int w = warp_sums[lane];
            int xs = w;
#pragma unroll
            for (int off = 1; off < 32; off <<= 1) {
                int y = __shfl_up_sync(0xFFFFFFFFu, xs, off);
                if (lane >= off) xs += y;
            }
            warp_sums[lane] = xs - w;  // exclusive warp offsets
        }
        __syncthreads();

        int excl = s_carry + warp_sums[wid] + (x - tsum);
        int run = excl;
#pragma unroll
        for (int j = 0; j < 4; j++) {
            int i = i0 + j;
            if (i < NN) { g_off[i] = run; g_cur[i] = run; }
            run += v[j];
        }
        __syncthreads();  // everyone has consumed s_carry / warp_sums
        if (tid == 1023) s_carry = excl + tsum;  // = old carry + chunk total
        __syncthreads();
    }
    if (tid == 0) g_off[NN] = s_carry;
}

__global__ void scatter_kernel(const int* __restrict__ src, const int* __restrict__ dst) {
    int e = blockIdx.x * blockDim.x + threadIdx.x;
    if (e < NE) {
        int pos = atomicAdd(&g_cur[dst[e]], 1);
        g_esrc[pos] = src[e];
    }
}

// ---------------- neighbor aggregation: one warp per node, float2/lane ----------------
__global__ __launch_bounds__(256) void aggregate_kernel(const float* __restrict__ h) {
    int gw = (blockIdx.x * blockDim.x + threadIdx.x) >> 5;
    if (gw >= NN) return;
    int lane = threadIdx.x & 31;
    int e = g_off[gw];
    int e1 = g_off[gw + 1];
    float ax = 0.0f, ay = 0.0f;
    for (; e + 1 < e1; e += 2) {
        int sA = __ldg(&g_esrc[e]);
        int sB = __ldg(&g_esrc[e + 1]);
        float2 vA = *(const float2*)(h + sA * HF + lane * 2);
        float2 vB = *(const float2*)(h + sB * HF + lane * 2);
        ax += vA.x + vB.x;
        ay += vA.y + vB.y;
    }
    if (e < e1) {
        int sA = __ldg(&g_esrc[e]);
        float2 vA = *(const float2*)(h + sA * HF + lane * 2);
        ax += vA.x;
        ay += vA.y;
    }
    float2 o = make_float2(ax, ay);
    *(float2*)(g_hn + gw * HF + lane * 2) = o;
}

// ---------------- dense layer: thread = node, f32x2 FMAs, W in smem ----------------
__device__ __forceinline__ void accum_row(unsigned long long acc[32], float x,
                                          const float* __restrict__ wrow) {
    unsigned long long xx = pack_dup(x);
    const ulonglong2* w2 = (const ulonglong2*)wrow;
#pragma unroll
    for (int i = 0; i < 16; i++) {
        ulonglong2 ww = w2[i];
        FMA2(acc[2 * i], xx, ww.x, acc[2 * i]);
        FMA2(acc[2 * i + 1], xx, ww.y, acc[2 * i + 1]);
    }
}

// ACT: 0 = relu, 1 = sigmoid
template <int ACT>
__global__ __launch_bounds__(128) void gemm_kernel(const float* __restrict__ hin,
                                                   const float* __restrict__ W,   // [64][129]
                                                   const float* __restrict__ b,   // [64]
                                                   float* __restrict__ hout) {
    __shared__ float Wsm[129 * 64];  // Wsm[k*64 + j] = W[j*129 + k]
    for (int idx = threadIdx.x; idx < 129 * 64; idx += blockDim.x) {
        int k = idx >> 6, j = idx & 63;
        Wsm[idx] = __ldg(&W[j * 129 + k]);
    }
    __syncthreads();

    int n = blockIdx.x * 128 + threadIdx.x;
    if (n >= NN) return;

    unsigned long long acc[32];
    const unsigned long long* bp = (const unsigned long long*)b;
#pragma unroll
    for (int i = 0; i < 32; i++) acc[i] = __ldg(&bp[i]);

    const float* xh = hin + n * HF;
    const float* xn = g_hn + n * HF;

#pragma unroll 4
    for (int k = 0; k < 64; k++) accum_row(acc, __ldg(&xh[k]), &Wsm[k * 64]);
#pragma unroll 4
    for (int k = 0; k < 64; k++) accum_row(acc, xn[k], &Wsm[(64 + k) * 64]);
    accum_row(acc, g_he[n], &Wsm[128 * 64]);

    float* orow = hout + n * HF;
#pragma unroll
    for (int i = 0; i < 32; i++) {
        float v0, v1;
        unpack2(acc[i], v0, v1);
        if (ACT == 0) {
            v0 = fmaxf(v0, 0.0f);
            v1 = fmaxf(v1, 0.0f);
        } else {
            v0 = 1.0f / (1.0f + expf(-v0));
            v1 = 1.0f / (1.0f + expf(-v1));
        }
        float2 o = make_float2(v0, v1);
        *(float2*)(orow + i * 2) = o;
    }
}

// ---------------- final layer (2 outputs) via linearity trick ----------------
// out_init[n][c] = h[n].W2[c][0:64] + he[n]*W2[c][128] + b2[c]
// z[n][c]        = h[n].W2[c][64:128]   (to be scatter-added from src to dst)
__global__ __launch_bounds__(256) void final_self_kernel(const float* __restrict__ h,
                                                         const float* __restrict__ W2,
                                                         const float* __restrict__ b2,
                                                         float* __restrict__ out) {
    int n = blockIdx.x * blockDim.x + threadIdx.x;
    if (n >= NN) return;
    const float* x = h + n * HF;
    float s0 = 0.f, s1 = 0.f, z0 = 0.f, z1 = 0.f;
#pragma unroll 8
    for (int k = 0; k < 64; k++) {
        float xv = x[k];
        s0 += xv * __ldg(&W2[k]);
        s1 += xv * __ldg(&W2[129 + k]);
        z0 += xv * __ldg(&W2[64 + k]);
        z1 += xv * __ldg(&W2[129 + 64 + k]);
    }
    float hev = g_he[n];
    out[n * 2 + 0] = s0 + hev * __ldg(&W2[128]) + __ldg(&b2[0]);
    out[n * 2 + 1] = s1 + hev * __ldg(&W2[129 + 128]) + __ldg(&b2[1]);
    g_z[n * 2 + 0] = z0;
    g_z[n * 2 + 1] = z1;
}

__global__ void final_edge_kernel(const int* __restrict__ src, const int* __restrict__ dst,
                                  float* __restrict__ out) {
    int e = blockIdx.x * blockDim.x + threadIdx.x;
    if (e < NE) {
        int s = src[e];
        int d = dst[e];
        float2 zv = *(const float2*)(g_z + s * 2);
        atomicAdd(&out[d * 2 + 0], zv.x);
        atomicAdd(&out[d * 2 + 1], zv.y);
    }
}

// ---------------- launch ----------------
extern "C" void kernel_launch(void* const* d_in, const int* in_sizes, int n_in,
                              void* d_out, int out_size) {
    const float* node_feat = (const float*)d_in[0];
    const float* edge_feat = (const float*)d_in[1];
    const int*   src       = (const int*)d_in[2];
    const int*   dst       = (const int*)d_in[3];
    const float* W1        = (const float*)d_in[4];
    const float* b1        = (const float*)d_in[5];
    const float* Wmid      = (const float*)d_in[6];
    const float* bmid      = (const float*)d_in[7];
    const float* W2        = (const float*)d_in[8];
    const float* b2        = (const float*)d_in[9];
    float* out = (float*)d_out;

    void *pA = nullptr, *pB = nullptr;
    cudaGetSymbolAddress(&pA, g_hA);
    cudaGetSymbolAddress(&pB, g_hB);
    float* hA = (float*)pA;
    float* hB = (float*)pB;

    const int NB_NODE = (NN + 255) / 256;
    const int NB_EDGE = (NE + 511) / 512;
    const int NB_AGG  = (NN * 32 + 255) / 256;
    const int NB_GEMM = (NN + 127) / 128;

    // CSR + constant edge aggregate (he)
    zero_kernel<<<NB_NODE, 256>>>();
    hist_kernel<<<NB_EDGE, 512>>>(dst, edge_feat);
    scan_kernel<<<1, 1024>>>();
    scatter_kernel<<<NB_EDGE, 512>>>(src, dst);

    // Layer 1: node_feat -> hA (relu)
    aggregate_kernel<<<NB_AGG, 256>>>(node_feat);
    gemm_kernel<0><<<NB_GEMM, 128>>>(node_feat, W1, b1, hA);

    // Mid layers 0..4: relu for i<4, sigmoid for i==4. Ping-pong hA/hB.
    const float* cur = hA;
    float* nxt = hB;
    for (int i = 0; i < 5; i++) {
        aggregate_kernel<<<NB_AGG, 256>>>(cur);
        const float* Wi = Wmid + i * 64 * 129;
        const float* bi = bmid + i * 64;
        if (i < 4)
            gemm_kernel<0><<<NB_GEMM, 128>>>(cur, Wi, bi, nxt);
        else
            gemm_kernel<1><<<NB_GEMM, 128>>>(cur, Wi, bi, nxt);
        const float* t = cur;
        cur = nxt;
        nxt = (float*)t;
    }

    // Final layer: project to 2 dims first, then 8B/edge scatter-add.
    final_self_kernel<<<NB_NODE, 256>>>(cur, W2, b2, out);
    final_edge_kernel<<<NB_EDGE, 512>>>(src, dst, out);
}

// round 9
// speedup vs baseline: 1.0840x; 1.0840x over previous
#include <cuda_runtime.h>
#include <cstdint>
#include <math.h>

#define NN 50000
#define NE 800000
#define HF 64

// ---------------- scratch (static device globals; no allocs) ----------------
__device__ __align__(256) float g_hA[NN * HF];
__device__ __align__(256) float g_hB[NN * HF];
__device__ __align__(256) float g_hn[NN * HF];
__device__ float g_he[NN];
__device__ float g_z[NN * 2];
__device__ int g_deg[NN];
__device__ int g_off[NN + 1];
__device__ int g_cur[NN];
__device__ int g_esrc[NE];

// ---------------- packed f32x2 helpers ----------------
#define FMA2(d, a, b, c) \
    asm("fma.rn.f32x2 %0, %1, %2, %3;" : "=l"(d) : "l"(a), "l"(b), "l"(c))

__device__ __forceinline__ unsigned long long pack_dup(float x) {
    unsigned long long r;
    unsigned int u = __float_as_uint(x);
    asm("mov.b64 %0, {%1, %1};" : "=l"(r) : "r"(u));
    return r;
}
__device__ __forceinline__ void unpack2(unsigned long long v, float& lo, float& hi) {
    unsigned int a, b;
    asm("mov.b64 {%0, %1}, %2;" : "=r"(a), "=r"(b) : "l"(v));
    lo = __uint_as_float(a);
    hi = __uint_as_float(b);
}

// ---------------- CSR build ----------------
__global__ void zero_kernel() {
    int i = blockIdx.x * blockDim.x + threadIdx.x;
    if (i < NN) { g_deg[i] = 0; g_he[i] = 0.0f; }
}

__global__ void hist_kernel(const int* __restrict__ dst, const float* __restrict__ ef) {
    int e = blockIdx.x * blockDim.x + threadIdx.x;
    if (e < NE) {
        int d = dst[e];
        atomicAdd(&g_deg[d], 1);
        atomicAdd(&g_he[d], ef[e]);
    }
}

// Single-block exclusive scan of g_deg -> g_off / g_cur (warp-shuffle based).
__global__ __launch_bounds__(1024) void scan_kernel() {
    __shared__ int warp_sums[32];
    __shared__ int s_carry;
    const int tid = threadIdx.x;
    const int lane = tid & 31;
    const int wid = tid >> 5;
    if (tid == 0) s_carry = 0;
    __syncthreads();

    const int CHUNK = 1024 * 4;
    for (int base = 0; base < NN; base += CHUNK) {
        int v[4];
        int i0 = base + tid * 4;
#pragma unroll
        for (int j = 0; j < 4; j++) {
            int i = i0 + j;
            v[j] = (i < NN) ? g_deg[i] : 0;
        }
        int tsum = v[0] + v[1] + v[2] + v[3];

        int x = tsum;  // inclusive warp scan of thread sums
#pragma unroll
        for (int off = 1; off < 32; off <<= 1) {
            int y = __shfl_up_sync(0xFFFFFFFFu, x, off);
            if (lane >= off) x += y;
        }
        if (lane == 31) warp_sums[wid] = x;
        __syncthreads();
        if (wid == 0) {
            int w = warp_sums[lane];
            int xs = w;
#pragma unroll
            for (int off = 1; off < 32; off <<= 1) {
                int y = __shfl_up_sync(0xFFFFFFFFu, xs, off);
                if (lane >= off) xs += y;
            }
            warp_sums[lane] = xs - w;  // exclusive warp offsets
        }
        __syncthreads();

        int excl = s_carry + warp_sums[wid] + (x - tsum);
        int run = excl;
#pragma unroll
        for (int j = 0; j < 4; j++) {
            int i = i0 + j;
            if (i < NN) { g_off[i] = run; g_cur[i] = run; }
            run += v[j];
        }
        __syncthreads();  // everyone has consumed s_carry / warp_sums
        if (tid == 1023) s_carry = excl + tsum;  // = old carry + chunk total
        __syncthreads();
    }
    if (tid == 0) g_off[NN] = s_carry;
}

__global__ void scatter_kernel(const int* __restrict__ src, const int* __restrict__ dst) {
    int e = blockIdx.x * blockDim.x + threadIdx.x;
    if (e < NE) {
        int pos = atomicAdd(&g_cur[dst[e]], 1);
        g_esrc[pos] = src[e];
    }
}

// ---------------- neighbor aggregation ----------------
// One warp per node, float2 per lane. 4-deep unroll with 4 independent
// accumulator pairs: 4 gather rows in flight per warp (MLP 2 -> 4+) and no
// serial dependence between consecutive edge rows.
__global__ __launch_bounds__(256) void aggregate_kernel(const float* __restrict__ h) {
    int gw = (blockIdx.x * blockDim.x + threadIdx.x) >> 5;
    if (gw >= NN) return;
    int lane = threadIdx.x & 31;
    int e = __ldg(&g_off[gw]);
    int e1 = __ldg(&g_off[gw + 1]);
    const float* __restrict__ hl = h + lane * 2;

    float ax0 = 0.f, ay0 = 0.f, ax1 = 0.f, ay1 = 0.f;
    float ax2 = 0.f, ay2 = 0.f, ax3 = 0.f, ay3 = 0.f;

    for (; e + 3 < e1; e += 4) {
        int s0 = __ldg(&g_esrc[e]);
        int s1 = __ldg(&g_esrc[e + 1]);
        int s2 = __ldg(&g_esrc[e + 2]);
        int s3 = __ldg(&g_esrc[e + 3]);
        float2 v0 = *(const float2*)(hl + s0 * HF);
        float2 v1 = *(const float2*)(hl + s1 * HF);
        float2 v2 = *(const float2*)(hl + s2 * HF);
        float2 v3 = *(const float2*)(hl + s3 * HF);
        ax0 += v0.x; ay0 += v0.y;
        ax1 += v1.x; ay1 += v1.y;
        ax2 += v2.x; ay2 += v2.y;
        ax3 += v3.x; ay3 += v3.y;
    }
    for (; e < e1; e++) {
        int s0 = __ldg(&g_esrc[e]);
        float2 v0 = *(const float2*)(hl + s0 * HF);
        ax0 += v0.x; ay0 += v0.y;
    }
    float2 o = make_float2((ax0 + ax1) + (ax2 + ax3), (ay0 + ay1) + (ay2 + ay3));
    *(float2*)(g_hn + gw * HF + lane * 2) = o;
}

// ---------------- dense layer ----------------
// 2 threads per node (32 outputs each): acc[16] = 32 fp32 regs, no spill risk.
// Block = 256 threads -> 128 nodes. half = tid>>7 so each warp is half-uniform
// and smem weight reads are single-address broadcasts.
__device__ __forceinline__ void accum_row16(unsigned long long acc[16], float x,
                                            const float* __restrict__ wrow) {
    unsigned long long xx = pack_dup(x);
    const ulonglong2* w2 = (const ulonglong2*)wrow;
#pragma unroll
    for (int i = 0; i < 8; i++) {
        ulonglong2 ww = w2[i];
        FMA2(acc[2 * i], xx, ww.x, acc[2 * i]);
        FMA2(acc[2 * i + 1], xx, ww.y, acc[2 * i + 1]);
    }
}

// ACT: 0 = relu, 1 = sigmoid
template <int ACT>
__global__ __launch_bounds__(256) void gemm_kernel(const float* __restrict__ hin,
                                                   const float* __restrict__ W,   // [64][129]
                                                   const float* __restrict__ b,   // [64]
                                                   float* __restrict__ hout) {
    __shared__ float Wsm[129 * 64];  // Wsm[k*64 + j] = W[j*129 + k]
    for (int idx = threadIdx.x; idx < 129 * 64; idx += blockDim.x) {
        int k = idx >> 6, j = idx & 63;
        Wsm[idx] = __ldg(&W[j * 129 + k]);
    }
    __syncthreads();

    const int half = threadIdx.x >> 7;          // 0 or 1: which 32 outputs
    const int n = blockIdx.x * 128 + (threadIdx.x & 127);
    if (n >= NN) return;

    unsigned long long acc[16];
    const unsigned long long* bp = (const unsigned long long*)b + half * 16;
#pragma unroll
    for (int i = 0; i < 16; i++) acc[i] = __ldg(&bp[i]);

    const float* xh = hin + n * HF;
    const float* xn = g_hn + n * HF;
    const float* wbase = Wsm + half * 32;

#pragma unroll 4
    for (int k = 0; k < 64; k += 4) {
        float4 xv = __ldg((const float4*)(xh + k));
        accum_row16(acc, xv.x, wbase + (k + 0) * 64);
        accum_row16(acc, xv.y, wbase + (k + 1) * 64);
        accum_row16(acc, xv.z, wbase + (k + 2) * 64);
        accum_row16(acc, xv.w, wbase + (k + 3) * 64);
    }
#pragma unroll 4
    for (int k = 0; k < 64; k += 4) {
        float4 xv = *(const float4*)(xn + k);
        accum_row16(acc, xv.x, wbase + (64 + k + 0) * 64);
        accum_row16(acc, xv.y, wbase + (64 + k + 1) * 64);
        accum_row16(acc, xv.z, wbase + (64 + k + 2) * 64);
        accum_row16(acc, xv.w, wbase + (64 + k + 3) * 64);
    }
    accum_row16(acc, g_he[n], wbase + 128 * 64);

    float* orow = hout + n * HF + half * 32;
#pragma unroll
    for (int i = 0; i < 16; i++) {
        float v0, v1;
        unpack2(acc[i], v0, v1);
        if (ACT == 0) {
            v0 = fmaxf(v0, 0.0f);
            v1 = fmaxf(v1, 0.0f);
        } else {
            v0 = 1.0f / (1.0f + expf(-v0));
            v1 = 1.0f / (1.0f + expf(-v1));
        }
        float2 o = make_float2(v0, v1);
        *(float2*)(orow + i * 2) = o;
    }
}

// ---------------- final layer (2 outputs) via linearity trick ----------------
__global__ __launch_bounds__(256) void final_self_kernel(const float* __restrict__ h,
                                                         const float* __restrict__ W2,
                                                         const float* __restrict__ b2,
                                                         float* __restrict__ out) {
    int n = blockIdx.x * blockDim.x + threadIdx.x;
    if (n >= NN) return;
    const float* x = h + n * HF;
    float s0 = 0.f, s1 = 0.f, z0 = 0.f, z1 = 0.f;
#pragma unroll 8
    for (int k = 0; k < 64; k++) {
        float xv = x[k];
        s0 += xv * __ldg(&W2[k]);
        s1 += xv * __ldg(&W2[129 + k]);
        z0 += xv * __ldg(&W2[64 + k]);
        z1 += xv * __ldg(&W2[129 + 64 + k]);
    }
    float hev = g_he[n];
    out[n * 2 + 0] = s0 + hev * __ldg(&W2[128]) + __ldg(&b2[0]);
    out[n * 2 + 1] = s1 + hev * __ldg(&W2[129 + 128]) + __ldg(&b2[1]);
    g_z[n * 2 + 0] = z0;
    g_z[n * 2 + 1] = z1;
}

__global__ void final_edge_kernel(const int* __restrict__ src, const int* __restrict__ dst,
                                  float* __restrict__ out) {
    int e = blockIdx.x * blockDim.x + threadIdx.x;
    if (e < NE) {
        int s = src[e];
        int d = dst[e];
        float2 zv = *(const float2*)(g_z + s * 2);
        atomicAdd(&out[d * 2 + 0], zv.x);
        atomicAdd(&out[d * 2 + 1], zv.y);
    }
}

// ---------------- launch ----------------
extern "C" void kernel_launch(void* const* d_in, const int* in_sizes, int n_in,
                              void* d_out, int out_size) {
    const float* node_feat = (const float*)d_in[0];
    const float* edge_feat = (const float*)d_in[1];
    const int*   src       = (const int*)d_in[2];
    const int*   dst       = (const int*)d_in[3];
    const float* W1        = (const float*)d_in[4];
    const float* b1        = (const float*)d_in[5];
    const float* Wmid      = (const float*)d_in[6];
    const float* bmid      = (const float*)d_in[7];
    const float* W2        = (const float*)d_in[8];
    const float* b2        = (const float*)d_in[9];
    float* out = (float*)d_out;

    void *pA = nullptr, *pB = nullptr;
    cudaGetSymbolAddress(&pA, g_hA);
    cudaGetSymbolAddress(&pB, g_hB);
    float* hA = (float*)pA;
    float* hB = (float*)pB;

    const int NB_NODE = (NN + 255) / 256;
    const int NB_EDGE = (NE + 511) / 512;
    const int NB_AGG  = (NN * 32 + 255) / 256;
    const int NB_GEMM = (NN + 127) / 128;

    // CSR + constant edge aggregate (he)
    zero_kernel<<<NB_NODE, 256>>>();
    hist_kernel<<<NB_EDGE, 512>>>(dst, edge_feat);
    scan_kernel<<<1, 1024>>>();
    scatter_kernel<<<NB_EDGE, 512>>>(src, dst);

    // Layer 1: node_feat -> hA (relu)
    aggregate_kernel<<<NB_AGG, 256>>>(node_feat);
    gemm_kernel<0><<<NB_GEMM, 256>>>(node_feat, W1, b1, hA);

    // Mid layers 0..4: relu for i<4, sigmoid for i==4. Ping-pong hA/hB.
    const float* cur = hA;
    float* nxt = hB;
    for (int i = 0; i < 5; i++) {
        aggregate_kernel<<<NB_AGG, 256>>>(cur);
        const float* Wi = Wmid + i * 64 * 129;
        const float* bi = bmid + i * 64;
        if (i < 4)
            gemm_kernel<0><<<NB_GEMM, 256>>>(cur, Wi, bi, nxt);
        else
            gemm_kernel<1><<<NB_GEMM, 256>>>(cur, Wi, bi, nxt);
        const float* t = cur;
        cur = nxt;
        nxt = (float*)t;
    }

    // Final layer: project to 2 dims first, then 8B/edge scatter-add.
    final_self_kernel<<<NB_NODE, 256>>>(cur, W2, b2, out);
    final_edge_kernel<<<NB_EDGE, 512>>>(src, dst, out);
}

// round 10
// speedup vs baseline: 1.2866x; 1.1869x over previous
#include <cuda_runtime.h>
#include <cstdint>
#include <math.h>

#define NN 50000
#define NE 800000
#define HF 64

// ---------------- scratch (static device globals; no allocs) ----------------
__device__ __align__(256) float g_hA[NN * HF];
__device__ __align__(256) float g_hB[NN * HF];
__device__ __align__(256) float g_hn[NN * HF];
__device__ float g_he[NN];
__device__ float g_z[NN * 2];
__device__ int g_deg[NN];
__device__ int g_off[NN + 1];
__device__ int g_cur[NN];
__device__ int g_esrc[NE];

// ---------------- packed f32x2 helpers ----------------
#define FMA2(d, a, b, c) \
    asm("fma.rn.f32x2 %0, %1, %2, %3;" : "=l"(d) : "l"(a), "l"(b), "l"(c))

__device__ __forceinline__ unsigned long long pack_dup(float x) {
    unsigned long long r;
    unsigned int u = __float_as_uint(x);
    asm("mov.b64 %0, {%1, %1};" : "=l"(r) : "r"(u));
    return r;
}
__device__ __forceinline__ void unpack2(unsigned long long v, float& lo, float& hi) {
    unsigned int a, b;
    asm("mov.b64 {%0, %1}, %2;" : "=r"(a), "=r"(b) : "l"(v));
    lo = __uint_as_float(a);
    hi = __uint_as_float(b);
}

// ---------------- CSR build ----------------
__global__ void zero_kernel() {
    int i = blockIdx.x * blockDim.x + threadIdx.x;
    if (i < NN) { g_deg[i] = 0; g_he[i] = 0.0f; }
}

__global__ void hist_kernel(const int* __restrict__ dst, const float* __restrict__ ef) {
    int e = blockIdx.x * blockDim.x + threadIdx.x;
    if (e < NE) {
        int d = dst[e];
        atomicAdd(&g_deg[d], 1);
        atomicAdd(&g_he[d], ef[e]);
    }
}

// Single-block exclusive scan of g_deg -> g_off / g_cur (warp-shuffle based).
__global__ __launch_bounds__(1024) void scan_kernel() {
    __shared__ int warp_sums[32];
    __shared__ int s_carry;
    const int tid = threadIdx.x;
    const int lane = tid & 31;
    const int wid = tid >> 5;
    if (tid == 0) s_carry = 0;
    __syncthreads();

    const int CHUNK = 1024 * 4;
    for (int base = 0; base < NN; base += CHUNK) {
        int v[4];
        int i0 = base + tid * 4;
#pragma unroll
        for (int j = 0; j < 4; j++) {
            int i = i0 + j;
            v[j] = (i < NN) ? g_deg[i] : 0;
        }
        int tsum = v[0] + v[1] + v[2] + v[3];

        int x = tsum;  // inclusive warp scan of thread sums
#pragma unroll
        for (int off = 1; off < 32; off <<= 1) {
            int y = __shfl_up_sync(0xFFFFFFFFu, x, off);
            if (lane >= off) x += y;
        }
        if (lane == 31) warp_sums[wid] = x;
        __syncthreads();
        if (wid == 0) {
            int w = warp_sums[lane];
            int xs = w;
#pragma unroll
            for (int off = 1; off < 32; off <<= 1) {
                int y = __shfl_up_sync(0xFFFFFFFFu, xs, off);
                if (lane >= off) xs += y;
            }
            warp_sums[lane] = xs - w;  // exclusive warp offsets
        }
        __syncthreads();

        int excl = s_carry + warp_sums[wid] + (x - tsum);
        int run = excl;
#pragma unroll
        for (int j = 0; j < 4; j++) {
            int i = i0 + j;
            if (i < NN) { g_off[i] = run; g_cur[i] = run; }
            run += v[j];
        }
        __syncthreads();  // everyone has consumed s_carry / warp_sums
        if (tid == 1023) s_carry = excl + tsum;  // = old carry + chunk total
        __syncthreads();
    }
    if (tid == 0) g_off[NN] = s_carry;
}

__global__ void scatter_kernel(const int* __restrict__ src, const int* __restrict__ dst) {
    int e = blockIdx.x * blockDim.x + threadIdx.x;
    if (e < NE) {
        int pos = atomicAdd(&g_cur[dst[e]], 1);
        g_esrc[pos] = src[e];
    }
}

// ---------------- neighbor aggregation ----------------
// One warp per node, float2 per lane, 4 independent accumulator pairs (MLP 4).
__global__ __launch_bounds__(256) void aggregate_kernel(const float* __restrict__ h) {
    int gw = (blockIdx.x * blockDim.x + threadIdx.x) >> 5;
    if (gw >= NN) return;
    int lane = threadIdx.x & 31;
    int e = __ldg(&g_off[gw]);
    int e1 = __ldg(&g_off[gw + 1]);
    const float* __restrict__ hl = h + lane * 2;

    float ax0 = 0.f, ay0 = 0.f, ax1 = 0.f, ay1 = 0.f;
    float ax2 = 0.f, ay2 = 0.f, ax3 = 0.f, ay3 = 0.f;

    for (; e + 3 < e1; e += 4) {
        int s0 = __ldg(&g_esrc[e]);
        int s1 = __ldg(&g_esrc[e + 1]);
        int s2 = __ldg(&g_esrc[e + 2]);
        int s3 = __ldg(&g_esrc[e + 3]);
        float2 v0 = *(const float2*)(hl + s0 * HF);
        float2 v1 = *(const float2*)(hl + s1 * HF);
        float2 v2 = *(const float2*)(hl + s2 * HF);
        float2 v3 = *(const float2*)(hl + s3 * HF);
        ax0 += v0.x; ay0 += v0.y;
        ax1 += v1.x; ay1 += v1.y;
        ax2 += v2.x; ay2 += v2.y;
        ax3 += v3.x; ay3 += v3.y;
    }
    for (; e < e1; e++) {
        int s0 = __ldg(&g_esrc[e]);
        float2 v0 = *(const float2*)(hl + s0 * HF);
        ax0 += v0.x; ay0 += v0.y;
    }
    float2 o = make_float2((ax0 + ax1) + (ax2 + ax3), (ay0 + ay1) + (ay2 + ay3));
    *(float2*)(g_hn + gw * HF + lane * 2) = o;
}

// ---------------- dense layer (fully coalesced, smem-staged) ----------------
// 256 threads, 128 nodes/block, 2 threads per node (half = tid>>7, 32 outputs).
// Dynamic smem:
//   Wsm  [129 * 68]  pitch 68: Wsm[k*68 + j] = W[j*129 + k]   (35,088 B... region 129*68)
//   stg  [128 * 68]  pitch 68: staging for inputs & outputs
// Pitch 68 floats = 272 B: multiple of 16 B (float4/ulonglong2 aligned), and
// 272 mod 128 = 16 -> per-thread row accesses spread over 8 bank groups
// (<=4-way conflict) instead of 32-way at pitch 64.
#define WPITCH 68
#define GEMM_SMEM ((129 * WPITCH + 128 * WPITCH) * 4)

__device__ __forceinline__ void accum_row16(unsigned long long acc[16], float x,
                                            const float* wrow) {
    unsigned long long xx = pack_dup(x);
    const ulonglong2* w2 = (const ulonglong2*)wrow;
#pragma unroll
    for (int i = 0; i < 8; i++) {
        ulonglong2 ww = w2[i];
        FMA2(acc[2 * i], xx, ww.x, acc[2 * i]);
        FMA2(acc[2 * i + 1], xx, ww.y, acc[2 * i + 1]);
    }
}

// ACT: 0 = relu, 1 = sigmoid
template <int ACT>
__global__ __launch_bounds__(256) void gemm_kernel(const float* __restrict__ hin,
                                                   const float* __restrict__ W,   // [64][129]
                                                   const float* __restrict__ b,   // [64]
                                                   float* __restrict__ hout) {
    extern __shared__ float sm[];
    float* Wsm = sm;                  // [129][WPITCH]
    float* stg = sm + 129 * WPITCH;   // [128][WPITCH]
    const int tid = threadIdx.x;
    const int base_n = blockIdx.x * 128;

    // 1) W: coalesced linear read, transposed smem write (2-way STS conflict).
    for (int idx = tid; idx < 129 * 64; idx += 256) {
        int j = idx / 129;
        int k = idx - j * 129;
        Wsm[k * WPITCH + j] = __ldg(&W[idx]);
    }

    // 2) Stage xh rows (coalesced float4 global reads).
    for (int idx = tid; idx < 128 * 16; idx += 256) {
        int nl = idx >> 4, q = idx & 15;
        int n = base_n + nl;
        float4 v = (n < NN) ? __ldg((const float4*)(hin + n * HF + q * 4))
                            : make_float4(0.f, 0.f, 0.f, 0.f);
        *(float4*)&stg[nl * WPITCH + q * 4] = v;
    }
    __syncthreads();

    const int half = tid >> 7;           // 0 or 1: which 32 outputs
    const int nl = tid & 127;            // local node
    const int n = base_n + nl;

    unsigned long long acc[16];
    const unsigned long long* bp = (const unsigned long long*)b + half * 16;
#pragma unroll
    for (int i = 0; i < 16; i++) acc[i] = __ldg(&bp[i]);

    const float* wbase = Wsm + half * 32;
    const float* xrow = stg + nl * WPITCH;

#pragma unroll 4
    for (int k = 0; k < 64; k += 4) {
        float4 xv = *(const float4*)(xrow + k);
        accum_row16(acc, xv.x, wbase + (k + 0) * WPITCH);
        accum_row16(acc, xv.y, wbase + (k + 1) * WPITCH);
        accum_row16(acc, xv.z, wbase + (k + 2) * WPITCH);
        accum_row16(acc, xv.w, wbase + (k + 3) * WPITCH);
    }
    __syncthreads();

    // 3) Stage xn rows (g_hn, coalesced) and accumulate.
    for (int idx = tid; idx < 128 * 16; idx += 256) {
        int nli = idx >> 4, q = idx & 15;
        int ni = base_n + nli;
        float4 v = (ni < NN) ? *(const float4*)(g_hn + ni * HF + q * 4)
                             : make_float4(0.f, 0.f, 0.f, 0.f);
        *(float4*)&stg[nli * WPITCH + q * 4] = v;
    }
    __syncthreads();

#pragma unroll 4
    for (int k = 0; k < 64; k += 4) {
        float4 xv = *(const float4*)(xrow + k);
        accum_row16(acc, xv.x, wbase + (64 + k + 0) * WPITCH);
        accum_row16(acc, xv.y, wbase + (64 + k + 1) * WPITCH);
        accum_row16(acc, xv.z, wbase + (64 + k + 2) * WPITCH);
        accum_row16(acc, xv.w, wbase + (64 + k + 3) * WPITCH);
    }
    float hev = (n < NN) ? g_he[n] : 0.f;  // warp reads 32 consecutive -> coalesced
    accum_row16(acc, hev, wbase + 128 * WPITCH);
    __syncthreads();

    // 4) Activation into staging (STS.64, bounded conflicts).
    float* srow = stg + nl * WPITCH + half * 32;
#pragma unroll
    for (int i = 0; i < 16; i++) {
        float v0, v1;
        unpack2(acc[i], v0, v1);
        if (ACT == 0) {
            v0 = fmaxf(v0, 0.0f);
            v1 = fmaxf(v1, 0.0f);
        } else {
            v0 = 1.0f / (1.0f + expf(-v0));
            v1 = 1.0f / (1.0f + expf(-v1));
        }
        *(float2*)(srow + i * 2) = make_float2(v0, v1);
    }
    __syncthreads();

    // 5) Coalesced float4 store to hout.
    for (int idx = tid; idx < 128 * 16; idx += 256) {
        int nli = idx >> 4, q = idx & 15;
        int ni = base_n + nli;
        if (ni < NN) {
            float4 v = *(const float4*)&stg[nli * WPITCH + q * 4];
            *(float4*)(hout + ni * HF + q * 4) = v;
        }
    }
}

// ---------------- final layer (2 outputs) via linearity trick ----------------
__global__ __launch_bounds__(256) void final_self_kernel(const float* __restrict__ h,
                                                         const float* __restrict__ W2,
                                                         const float* __restrict__ b2,
                                                         float* __restrict__ out) {
    int n = blockIdx.x * blockDim.x + threadIdx.x;
    if (n >= NN) return;
    const float* x = h + n * HF;
    float s0 = 0.f, s1 = 0.f, z0 = 0.f, z1 = 0.f;
#pragma unroll 8
    for (int k = 0; k < 64; k++) {
        float xv = x[k];
        s0 += xv * __ldg(&W2[k]);
        s1 += xv * __ldg(&W2[129 + k]);
        z0 += xv * __ldg(&W2[64 + k]);
        z1 += xv * __ldg(&W2[129 + 64 + k]);
    }
    float hev = g_he[n];
    out[n * 2 + 0] = s0 + hev * __ldg(&W2[128]) + __ldg(&b2[0]);
    out[n * 2 + 1] = s1 + hev * __ldg(&W2[129 + 128]) + __ldg(&b2[1]);
    g_z[n * 2 + 0] = z0;
    g_z[n * 2 + 1] = z1;
}

__global__ void final_edge_kernel(const int* __restrict__ src, const int* __restrict__ dst,
                                  float* __restrict__ out) {
    int e = blockIdx.x * blockDim.x + threadIdx.x;
    if (e < NE) {
        int s = src[e];
        int d = dst[e];
        float2 zv = *(const float2*)(g_z + s * 2);
        atomicAdd(&out[d * 2 + 0], zv.x);
        atomicAdd(&out[d * 2 + 1], zv.y);
    }
}

// ---------------- launch ----------------
extern "C" void kernel_launch(void* const* d_in, const int* in_sizes, int n_in,
                              void* d_out, int out_size) {
    const float* node_feat = (const float*)d_in[0];
    const float* edge_feat = (const float*)d_in[1];
    const int*   src       = (const int*)d_in[2];
    const int*   dst       = (const int*)d_in[3];
    const float* W1        = (const float*)d_in[4];
    const float* b1        = (const float*)d_in[5];
    const float* Wmid      = (const float*)d_in[6];
    const float* bmid      = (const float*)d_in[7];
    const float* W2        = (const float*)d_in[8];
    const float* b2        = (const float*)d_in[9];
    float* out = (float*)d_out;

    // Dynamic smem > 48KB: set attribute (idempotent, host-side, capture-safe).
    cudaFuncSetAttribute(gemm_kernel<0>, cudaFuncAttributeMaxDynamicSharedMemorySize, GEMM_SMEM);
    cudaFuncSetAttribute(gemm_kernel<1>, cudaFuncAttributeMaxDynamicSharedMemorySize, GEMM_SMEM);

    void *pA = nullptr, *pB = nullptr;
    cudaGetSymbolAddress(&pA, g_hA);
    cudaGetSymbolAddress(&pB, g_hB);
    float* hA = (float*)pA;
    float* hB = (float*)pB;

    const int NB_NODE = (NN + 255) / 256;
    const int NB_EDGE = (NE + 511) / 512;
    const int NB_AGG  = (NN * 32 + 255) / 256;
    const int NB_GEMM = (NN + 127) / 128;

    // CSR + constant edge aggregate (he)
    zero_kernel<<<NB_NODE, 256>>>();
    hist_kernel<<<NB_EDGE, 512>>>(dst, edge_feat);
    scan_kernel<<<1, 1024>>>();
    scatter_kernel<<<NB_EDGE, 512>>>(src, dst);

    // Layer 1: node_feat -> hA (relu)
    aggregate_kernel<<<NB_AGG, 256>>>(node_feat);
    gemm_kernel<0><<<NB_GEMM, 256, GEMM_SMEM>>>(node_feat, W1, b1, hA);

    // Mid layers 0..4: relu for i<4, sigmoid for i==4. Ping-pong hA/hB.
    const float* cur = hA;
    float* nxt = hB;
    for (int i = 0; i < 5; i++) {
        aggregate_kernel<<<NB_AGG, 256>>>(cur);
        const float* Wi = Wmid + i * 64 * 129;
        const float* bi = bmid + i * 64;
        if (i < 4)
            gemm_kernel<0><<<NB_GEMM, 256, GEMM_SMEM>>>(cur, Wi, bi, nxt);
        else
            gemm_kernel<1><<<NB_GEMM, 256, GEMM_SMEM>>>(cur, Wi, bi, nxt);
        const float* t = cur;
        cur = nxt;
        nxt = (float*)t;
    }

    // Final layer: project to 2 dims first, then 8B/edge scatter-add.
    final_self_kernel<<<NB_NODE, 256>>>(cur, W2, b2, out);
    final_edge_kernel<<<NB_EDGE, 512>>>(src, dst, out);
}